// round 1
// baseline (speedup 1.0000x reference)
#include <cuda_runtime.h>
#include <cuda_bf16.h>

// Problem constants
#define B_  4
#define N_  2048
#define C_  768
#define H_  12
#define HD_ 64
#define NC3 2304              // 3*C
#define SCALE_ 0.125f         // 64^-0.5

// Static scratch (allocation-free requirement): ~100 MB total
__device__ float g_q[(size_t)B_ * H_ * N_ * HD_];   // [B,H,N,HD]
__device__ float g_k[(size_t)B_ * H_ * N_ * HD_];
__device__ float g_v[(size_t)B_ * H_ * N_ * HD_];
__device__ float g_ao[(size_t)B_ * N_ * C_];        // [B,N,H*HD]

// ---------------------------------------------------------------------------
// Kernel 1: QKV GEMM  Y = X[8192,768] @ W[768,2304] + b, fused bias-inject +
// scatter into g_q/g_k/g_v in [B,H,N,HD] layout.
// 128x128 tile, BK=8, 256 threads, 8x8 per-thread micro-tile.
// ---------------------------------------------------------------------------
__global__ __launch_bounds__(256) void qkv_gemm(
    const float* __restrict__ X, const float* __restrict__ W,
    const float* __restrict__ bias,
    const float* __restrict__ qb, const float* __restrict__ kb,
    const float* __restrict__ vb)
{
    __shared__ __align__(16) float As[8][128];
    __shared__ __align__(16) float Bs[8][128];

    const int tid  = threadIdx.x;
    const int bx   = blockIdx.x;   // col tile (0..17)
    const int by   = blockIdx.y;   // row tile (0..63)
    const int trow = tid >> 4;     // 0..15
    const int tcol = tid & 15;     // 0..15

    float acc[8][8];
    #pragma unroll
    for (int i = 0; i < 8; i++)
        #pragma unroll
        for (int j = 0; j < 8; j++) acc[i][j] = 0.f;

    const int arow = tid >> 1;           // 0..127
    const int ak   = (tid & 1) * 4;      // 0 or 4
    const int bk   = tid >> 5;           // 0..7
    const int bc   = (tid & 31) * 4;     // 0..124

    const float* Aptr = X + ((size_t)(by * 128 + arow)) * C_ + ak;
    const float* Bptr = W + (size_t)bk * NC3 + bx * 128 + bc;

    for (int kt = 0; kt < C_; kt += 8) {
        float4 a = *(const float4*)(Aptr + kt);
        As[ak + 0][arow] = a.x;
        As[ak + 1][arow] = a.y;
        As[ak + 2][arow] = a.z;
        As[ak + 3][arow] = a.w;
        float4 bvec = *(const float4*)(Bptr + (size_t)kt * NC3);
        *(float4*)&Bs[bk][bc] = bvec;
        __syncthreads();

        #pragma unroll
        for (int k = 0; k < 8; k++) {
            float ra[8], rb[8];
            *(float4*)&ra[0] = *(const float4*)&As[k][trow * 8];
            *(float4*)&ra[4] = *(const float4*)&As[k][trow * 8 + 4];
            *(float4*)&rb[0] = *(const float4*)&Bs[k][tcol * 8];
            *(float4*)&rb[4] = *(const float4*)&Bs[k][tcol * 8 + 4];
            #pragma unroll
            for (int i = 0; i < 8; i++)
                #pragma unroll
                for (int j = 0; j < 8; j++)
                    acc[i][j] = fmaf(ra[i], rb[j], acc[i][j]);
        }
        __syncthreads();
    }

    // Epilogue: + b_qkv, + per-head bias, scatter to q/k/v
    const int gr0 = by * 128 + trow * 8;
    const int gc0 = bx * 128 + tcol * 8;
    #pragma unroll
    for (int i = 0; i < 8; i++) {
        int m  = gr0 + i;
        int bb = m >> 11;        // / 2048
        int n  = m & 2047;
        #pragma unroll
        for (int j = 0; j < 8; j++) {
            int col = gc0 + j;
            int s3  = col / C_;
            int rem = col - s3 * C_;
            int hh  = rem >> 6;
            int dd  = rem & 63;
            float v = acc[i][j] + bias[col];
            int idx = (((bb * H_) + hh) * N_ + n) * HD_ + dd;
            if (s3 == 0)      g_q[idx] = v + qb[idx];
            else if (s3 == 1) g_k[idx] = v + kb[idx];
            else              g_v[idx] = v + vb[idx];
        }
    }
}

// ---------------------------------------------------------------------------
// Kernel 2: fp32 flash attention. One q-row per thread (256 rows/CTA).
// Online softmax is fully thread-local; K/V staged through smem in 32-key
// chunks, consumed in 8-key register groups (broadcast LDS.128).
// Writes g_ao in [B,N,H*HD] layout.
// ---------------------------------------------------------------------------
__global__ __launch_bounds__(256, 1) void attn_kernel()
{
    __shared__ __align__(16) float Ks[32][64];
    __shared__ __align__(16) float Vs[32][64];

    const int tid = threadIdx.x;
    const int qt  = blockIdx.x;   // 0..7
    const int h   = blockIdx.y;   // 0..11
    const int b   = blockIdx.z;   // 0..3
    const int row = qt * 256 + tid;

    const size_t head_off = (((size_t)b * H_ + h) * N_) * HD_;
    const float* qptr  = g_q + head_off + (size_t)row * HD_;
    const float* kbase = g_k + head_off;
    const float* vbase = g_v + head_off;

    float4 q[16];
    #pragma unroll
    for (int i = 0; i < 16; i++) q[i] = ((const float4*)qptr)[i];

    float4 o[16];
    #pragma unroll
    for (int i = 0; i < 16; i++) o[i] = make_float4(0.f, 0.f, 0.f, 0.f);

    float m_ = -1e30f;
    float l_ = 0.f;

    for (int kt = 0; kt < N_; kt += 32) {
        // cooperative smem fill: 32 keys x 64 floats for K and V
        {
            const float4* ks4 = (const float4*)(kbase + (size_t)kt * HD_);
            const float4* vs4 = (const float4*)(vbase + (size_t)kt * HD_);
            float4* kd = (float4*)&Ks[0][0];
            float4* vd = (float4*)&Vs[0][0];
            kd[tid]       = ks4[tid];
            kd[tid + 256] = ks4[tid + 256];
            vd[tid]       = vs4[tid];
            vd[tid + 256] = vs4[tid + 256];
        }
        __syncthreads();

        #pragma unroll 1
        for (int jj = 0; jj < 32; jj += 8) {
            float s[8];
            #pragma unroll
            for (int j = 0; j < 8; j++) {
                const float4* kr = (const float4*)&Ks[jj + j][0];
                float ax = 0.f, ay = 0.f, az = 0.f, aw = 0.f;
                #pragma unroll
                for (int i = 0; i < 16; i++) {
                    float4 kk = kr[i];
                    ax = fmaf(q[i].x, kk.x, ax);
                    ay = fmaf(q[i].y, kk.y, ay);
                    az = fmaf(q[i].z, kk.z, az);
                    aw = fmaf(q[i].w, kk.w, aw);
                }
                s[j] = (ax + ay + az + aw) * SCALE_;
            }
            float mloc = fmaxf(fmaxf(fmaxf(s[0], s[1]), fmaxf(s[2], s[3])),
                               fmaxf(fmaxf(s[4], s[5]), fmaxf(s[6], s[7])));
            float mnew = fmaxf(m_, mloc);
            float corr = __expf(m_ - mnew);
            l_ *= corr;
            #pragma unroll
            for (int i = 0; i < 16; i++) {
                o[i].x *= corr; o[i].y *= corr; o[i].z *= corr; o[i].w *= corr;
            }
            #pragma unroll
            for (int j = 0; j < 8; j++) {
                float p = __expf(s[j] - mnew);
                l_ += p;
                const float4* vr = (const float4*)&Vs[jj + j][0];
                #pragma unroll
                for (int i = 0; i < 16; i++) {
                    float4 vv = vr[i];
                    o[i].x = fmaf(p, vv.x, o[i].x);
                    o[i].y = fmaf(p, vv.y, o[i].y);
                    o[i].z = fmaf(p, vv.z, o[i].z);
                    o[i].w = fmaf(p, vv.w, o[i].w);
                }
            }
            m_ = mnew;
        }
        __syncthreads();
    }

    const float inv = 1.f / l_;
    float* optr = g_ao + ((size_t)b * N_ + row) * C_ + h * HD_;
    #pragma unroll
    for (int i = 0; i < 16; i++) {
        float4 r = make_float4(o[i].x * inv, o[i].y * inv, o[i].z * inv, o[i].w * inv);
        ((float4*)optr)[i] = r;
    }
}

// ---------------------------------------------------------------------------
// Kernel 3: proj GEMM  out = g_ao[8192,768] @ Wp[768,768] + bp
// ---------------------------------------------------------------------------
__global__ __launch_bounds__(256) void proj_gemm(
    const float* __restrict__ Wp, const float* __restrict__ bp,
    float* __restrict__ out)
{
    __shared__ __align__(16) float As[8][128];
    __shared__ __align__(16) float Bs[8][128];

    const int tid  = threadIdx.x;
    const int bx   = blockIdx.x;   // col tile (0..5)
    const int by   = blockIdx.y;   // row tile (0..63)
    const int trow = tid >> 4;
    const int tcol = tid & 15;

    float acc[8][8];
    #pragma unroll
    for (int i = 0; i < 8; i++)
        #pragma unroll
        for (int j = 0; j < 8; j++) acc[i][j] = 0.f;

    const int arow = tid >> 1;
    const int ak   = (tid & 1) * 4;
    const int bk   = tid >> 5;
    const int bc   = (tid & 31) * 4;

    const float* Aptr = g_ao + ((size_t)(by * 128 + arow)) * C_ + ak;
    const float* Bptr = Wp + (size_t)bk * C_ + bx * 128 + bc;

    for (int kt = 0; kt < C_; kt += 8) {
        float4 a = *(const float4*)(Aptr + kt);
        As[ak + 0][arow] = a.x;
        As[ak + 1][arow] = a.y;
        As[ak + 2][arow] = a.z;
        As[ak + 3][arow] = a.w;
        float4 bvec = *(const float4*)(Bptr + (size_t)kt * C_);
        *(float4*)&Bs[bk][bc] = bvec;
        __syncthreads();

        #pragma unroll
        for (int k = 0; k < 8; k++) {
            float ra[8], rb[8];
            *(float4*)&ra[0] = *(const float4*)&As[k][trow * 8];
            *(float4*)&ra[4] = *(const float4*)&As[k][trow * 8 + 4];
            *(float4*)&rb[0] = *(const float4*)&Bs[k][tcol * 8];
            *(float4*)&rb[4] = *(const float4*)&Bs[k][tcol * 8 + 4];
            #pragma unroll
            for (int i = 0; i < 8; i++)
                #pragma unroll
                for (int j = 0; j < 8; j++)
                    acc[i][j] = fmaf(ra[i], rb[j], acc[i][j]);
        }
        __syncthreads();
    }

    const int gr0 = by * 128 + trow * 8;
    const int gc0 = bx * 128 + tcol * 8;
    #pragma unroll
    for (int i = 0; i < 8; i++) {
        int mrow = gr0 + i;
        #pragma unroll
        for (int j = 0; j < 8; j++) {
            int col = gc0 + j;
            out[(size_t)mrow * C_ + col] = acc[i][j] + bp[col];
        }
    }
}

// ---------------------------------------------------------------------------
extern "C" void kernel_launch(void* const* d_in, const int* in_sizes, int n_in,
                              void* d_out, int out_size)
{
    const float* x      = (const float*)d_in[0];
    const float* qbias  = (const float*)d_in[1];
    const float* kbias  = (const float*)d_in[2];
    const float* vbias  = (const float*)d_in[3];
    const float* W_qkv  = (const float*)d_in[4];
    const float* b_qkv  = (const float*)d_in[5];
    const float* W_proj = (const float*)d_in[6];
    const float* b_proj = (const float*)d_in[7];
    float* out = (float*)d_out;

    qkv_gemm<<<dim3(NC3 / 128, (B_ * N_) / 128), 256>>>(
        x, W_qkv, b_qkv, qbias, kbias, vbias);
    attn_kernel<<<dim3(N_ / 256, H_, B_), 256>>>();
    proj_gemm<<<dim3(C_ / 128, (B_ * N_) / 128), 256>>>(W_proj, b_proj, out);
}

// round 3
// speedup vs baseline: 3.1049x; 3.1049x over previous
#include <cuda_runtime.h>
#include <cuda_bf16.h>
#include <cstdint>

// Problem constants
#define B_  4
#define N_  2048
#define C_  768
#define H_  12
#define HD_ 64
#define NC3 2304
#define SCALE_ 0.125f

#define QKV_SZ ((size_t)B_ * H_ * N_ * HD_)   // 6291456

// Static scratch: bf16 hi/lo pairs for q,k,v; fp32 attention output
__device__ __nv_bfloat16 g_qhi[QKV_SZ], g_qlo[QKV_SZ];   // [B,H,N,HD], pre-scaled
__device__ __nv_bfloat16 g_khi[QKV_SZ], g_klo[QKV_SZ];   // [B,H,N,HD]
__device__ __nv_bfloat16 g_vhi[QKV_SZ], g_vlo[QKV_SZ];   // [B,H,HD,N] (transposed!)
__device__ float g_ao[(size_t)B_ * N_ * C_];              // [B,N,C]

// ---------------------------------------------------------------------------
// Helpers: portable tensor-core ISA (sm_80+, valid under plain sm_100)
// ---------------------------------------------------------------------------
__device__ __forceinline__ uint32_t smem_u32(const void* p) {
    uint32_t a;
    asm("{ .reg .u64 t; cvta.to.shared.u64 t, %1; cvt.u32.u64 %0, t; }"
        : "=r"(a) : "l"(p));
    return a;
}

__device__ __forceinline__ void ldmx4(uint32_t* r, uint32_t addr) {
    asm volatile("ldmatrix.sync.aligned.m8n8.x4.shared.b16 {%0,%1,%2,%3}, [%4];"
                 : "=r"(r[0]), "=r"(r[1]), "=r"(r[2]), "=r"(r[3]) : "r"(addr));
}
__device__ __forceinline__ void ldmx2t(uint32_t* r, uint32_t addr) {
    asm volatile("ldmatrix.sync.aligned.m8n8.x2.trans.shared.b16 {%0,%1}, [%2];"
                 : "=r"(r[0]), "=r"(r[1]) : "r"(addr));
}
__device__ __forceinline__ void mma16816(float* c, const uint32_t* a,
                                         const uint32_t* b) {
    asm volatile(
        "mma.sync.aligned.m16n8k16.row.col.f32.bf16.bf16.f32 "
        "{%0,%1,%2,%3}, {%4,%5,%6,%7}, {%8,%9}, {%0,%1,%2,%3};"
        : "+f"(c[0]), "+f"(c[1]), "+f"(c[2]), "+f"(c[3])
        : "r"(a[0]), "r"(a[1]), "r"(a[2]), "r"(a[3]), "r"(b[0]), "r"(b[1]));
}

// fp32 pair -> packed bf16 hi pair + lo (residual) pair
__device__ __forceinline__ void split2(float x, float y, uint32_t& hi, uint32_t& lo) {
    __nv_bfloat162 h = __floats2bfloat162_rn(x, y);
    float hx = __bfloat162float(h.x), hy = __bfloat162float(h.y);
    __nv_bfloat162 l = __floats2bfloat162_rn(x - hx, y - hy);
    hi = *(uint32_t*)&h;
    lo = *(uint32_t*)&l;
}

// ---------------------------------------------------------------------------
// Kernel 1/3: triple-bf16 HMMA GEMM. 128x128 CTA tile, 256 thr (8 warps 2x4,
// warp tile 64x32), K-stage 32, single smem buffer + register prefetch.
// MODE 0: qkv (A=x, epilogue -> hi/lo split q/k/v with biases, q*SCALE, v^T)
// MODE 1: proj (A=g_ao, epilogue -> d_out + b_proj)
// ---------------------------------------------------------------------------
#define ASTR 40     // A smem row stride (bf16 elems), 80B: conflict-free ldmatrix
#define BSTR 136    // B smem row stride, 272B

template <int MODE>
__global__ __launch_bounds__(256, 1) void tc_gemm(
    const float* __restrict__ Ain, const float* __restrict__ W, int ldb,
    const float* __restrict__ biasRow,
    const float* __restrict__ qb, const float* __restrict__ kb,
    const float* __restrict__ vb, float* __restrict__ outp)
{
    __shared__ __align__(16) __nv_bfloat16 sAh[128 * ASTR], sAl[128 * ASTR];
    __shared__ __align__(16) __nv_bfloat16 sBh[32 * BSTR],  sBl[32 * BSTR];

    const int tid = threadIdx.x, lid = tid & 31, wid = tid >> 5;
    const int wm = wid >> 2, wn = wid & 3;
    const int n0 = blockIdx.x * 128, m0 = blockIdx.y * 128;
    const float* A = (MODE == 1) ? g_ao : Ain;

    float c[4][4][4];
    #pragma unroll
    for (int i = 0; i < 4; i++)
        #pragma unroll
        for (int j = 0; j < 4; j++)
            #pragma unroll
            for (int k = 0; k < 4; k++) c[i][j][k] = 0.f;

    // prefetch mapping: A thread -> (row tid/2, k-half (tid&1)*16, 4xfloat4)
    //                   B thread -> (k-row tid/8, col 4*(tid&7) + 32j)
    const int ar = tid >> 1, akb = (tid & 1) * 16;
    const int br = tid >> 3, bcb = (tid & 7) * 4;
    const float* Ag = A + (size_t)(m0 + ar) * C_ + akb;
    const float* Bg = W + (size_t)br * ldb + n0 + bcb;

    float4 pa[4], pb[4];
    #pragma unroll
    for (int j = 0; j < 4; j++) {
        pa[j] = *(const float4*)(Ag + 4 * j);
        pb[j] = *(const float4*)(Bg + 32 * j);
    }

    const uint32_t aAh = smem_u32(sAh), aAl = smem_u32(sAl);
    const uint32_t aBh = smem_u32(sBh), aBl = smem_u32(sBl);

    for (int s = 0; s < C_ / 32; s++) {
        __syncthreads();
        #pragma unroll
        for (int j = 0; j < 4; j++) {
            uint32_t h0, l0v, h1, l1v;
            split2(pa[j].x, pa[j].y, h0, l0v);
            split2(pa[j].z, pa[j].w, h1, l1v);
            *(uint2*)&sAh[ar * ASTR + akb + 4 * j] = make_uint2(h0, h1);
            *(uint2*)&sAl[ar * ASTR + akb + 4 * j] = make_uint2(l0v, l1v);
            split2(pb[j].x, pb[j].y, h0, l0v);
            split2(pb[j].z, pb[j].w, h1, l1v);
            *(uint2*)&sBh[br * BSTR + bcb + 32 * j] = make_uint2(h0, h1);
            *(uint2*)&sBl[br * BSTR + bcb + 32 * j] = make_uint2(l0v, l1v);
        }
        __syncthreads();
        if (s + 1 < C_ / 32) {
            #pragma unroll
            for (int j = 0; j < 4; j++) {
                pa[j] = *(const float4*)(Ag + (s + 1) * 32 + 4 * j);
                pb[j] = *(const float4*)(Bg + (size_t)(s + 1) * 32 * ldb + 32 * j);
            }
        }
        #pragma unroll
        for (int kk = 0; kk < 2; kk++) {
            const int k0 = kk * 16;
            uint32_t ah[4][4], al[4][4];
            #pragma unroll
            for (int mt = 0; mt < 4; mt++) {
                int row = wm * 64 + mt * 16 + (lid & 15);
                int col = k0 + ((lid >> 4) << 3);
                ldmx4(ah[mt], aAh + (uint32_t)(row * ASTR + col) * 2);
                ldmx4(al[mt], aAl + (uint32_t)(row * ASTR + col) * 2);
            }
            uint32_t bh[4][2], bl[4][2];
            #pragma unroll
            for (int nt = 0; nt < 4; nt++) {
                int kr = k0 + (lid & 15);
                int col = wn * 32 + nt * 8;
                ldmx2t(bh[nt], aBh + (uint32_t)(kr * BSTR + col) * 2);
                ldmx2t(bl[nt], aBl + (uint32_t)(kr * BSTR + col) * 2);
            }
            #pragma unroll
            for (int mt = 0; mt < 4; mt++)
                #pragma unroll
                for (int nt = 0; nt < 4; nt++) {
                    mma16816(c[mt][nt], ah[mt], bh[nt]);
                    mma16816(c[mt][nt], al[mt], bh[nt]);
                    mma16816(c[mt][nt], ah[mt], bl[nt]);
                }
        }
    }

    // Epilogue (direct from fragments)
    const int g = lid >> 2, t4 = lid & 3;
    if (MODE == 0) {
        const int s3 = n0 / C_;
        const int loc0 = n0 - s3 * C_;
        #pragma unroll
        for (int mt = 0; mt < 4; mt++) {
            #pragma unroll
            for (int nt = 0; nt < 4; nt++) {
                const int colT = wn * 32 + nt * 8 + 2 * t4;
                const int loc = loc0 + colT;
                const int hh = loc >> 6, dd = loc & 63;
                const float b0v = biasRow[n0 + colT];
                const float b1v = biasRow[n0 + colT + 1];
                #pragma unroll
                for (int hf = 0; hf < 2; hf++) {
                    const int m = m0 + wm * 64 + mt * 16 + g + hf * 8;
                    const int bb = m >> 11, nn = m & 2047;
                    const size_t bidx =
                        (((size_t)bb * H_ + hh) * N_ + nn) * HD_ + dd;
                    float v0 = c[mt][nt][2 * hf] + b0v;
                    float v1 = c[mt][nt][2 * hf + 1] + b1v;
                    if (s3 == 0) {
                        v0 = (v0 + qb[bidx]) * SCALE_;
                        v1 = (v1 + qb[bidx + 1]) * SCALE_;
                        uint32_t hi, lo;
                        split2(v0, v1, hi, lo);
                        *(uint32_t*)&g_qhi[bidx] = hi;
                        *(uint32_t*)&g_qlo[bidx] = lo;
                    } else if (s3 == 1) {
                        v0 += kb[bidx];
                        v1 += kb[bidx + 1];
                        uint32_t hi, lo;
                        split2(v0, v1, hi, lo);
                        *(uint32_t*)&g_khi[bidx] = hi;
                        *(uint32_t*)&g_klo[bidx] = lo;
                    } else {
                        v0 += vb[bidx];
                        v1 += vb[bidx + 1];
                        const size_t vix =
                            (((size_t)bb * H_ + hh) * HD_ + dd) * N_ + nn;
                        __nv_bfloat16 h0 = __float2bfloat16_rn(v0);
                        __nv_bfloat16 h1 = __float2bfloat16_rn(v1);
                        g_vhi[vix] = h0;
                        g_vlo[vix] = __float2bfloat16_rn(v0 - __bfloat162float(h0));
                        g_vhi[vix + N_] = h1;
                        g_vlo[vix + N_] = __float2bfloat16_rn(v1 - __bfloat162float(h1));
                    }
                }
            }
        }
    } else {
        #pragma unroll
        for (int mt = 0; mt < 4; mt++)
            #pragma unroll
            for (int nt = 0; nt < 4; nt++) {
                const int colT = wn * 32 + nt * 8 + 2 * t4;
                const float b0v = biasRow[n0 + colT];
                const float b1v = biasRow[n0 + colT + 1];
                #pragma unroll
                for (int hf = 0; hf < 2; hf++) {
                    const int m = m0 + wm * 64 + mt * 16 + g + hf * 8;
                    float2 r;
                    r.x = c[mt][nt][2 * hf] + b0v;
                    r.y = c[mt][nt][2 * hf + 1] + b1v;
                    *(float2*)&outp[(size_t)m * C_ + n0 + colT] = r;
                }
            }
    }
}

// ---------------------------------------------------------------------------
// Kernel 2: HMMA flash attention. CTA = 128 q-rows, 8 warps x 16 rows.
// 64-key chunks; triple-bf16 QK^T and PV; online softmax on fragments.
// ---------------------------------------------------------------------------
#define KSTR 72   // smem row stride (bf16): 144B -> conflict-free ldmatrix

__global__ __launch_bounds__(256, 1) void attn_kernel()
{
    __shared__ __align__(16) __nv_bfloat16 sm[4 * 64 * KSTR];  // 36864B
    __nv_bfloat16* sKh = sm;
    __nv_bfloat16* sKl = sm + 64 * KSTR;
    __nv_bfloat16* sVh = sm + 2 * 64 * KSTR;
    __nv_bfloat16* sVl = sm + 3 * 64 * KSTR;
    __nv_bfloat16* sQh = sm;                 // Q staging aliases (pre-loop only)
    __nv_bfloat16* sQl = sm + 128 * KSTR;

    const int tid = threadIdx.x, lid = tid & 31, wq = tid >> 5;
    const int qt = blockIdx.x, h = blockIdx.y, b = blockIdx.z;
    const size_t hoff = (size_t)(b * H_ + h) * N_ * HD_;   // q,k base
    const size_t voff = (size_t)(b * H_ + h) * HD_ * N_;   // v^T base
    const int q0 = qt * 128;

    // ---- stage Q (hi/lo) and capture fragments in registers
    #pragma unroll
    for (int j = 0; j < 4; j++) {
        int cid = tid + 256 * j;
        int row = cid >> 3, off = (cid & 7) * 8;
        size_t ga = hoff + (size_t)(q0 + row) * HD_ + off;
        *(float4*)&sQh[row * KSTR + off] = *(const float4*)&g_qhi[ga];
        *(float4*)&sQl[row * KSTR + off] = *(const float4*)&g_qlo[ga];
    }
    __syncthreads();
    uint32_t aqh[4][4], aql[4][4];
    {
        const uint32_t bH = smem_u32(sQh), bL = smem_u32(sQl);
        int row = wq * 16 + (lid & 15);
        int colb = (lid >> 4) << 3;
        #pragma unroll
        for (int kk = 0; kk < 4; kk++) {
            ldmx4(aqh[kk], bH + (uint32_t)(row * KSTR + kk * 16 + colb) * 2);
            ldmx4(aql[kk], bL + (uint32_t)(row * KSTR + kk * 16 + colb) * 2);
        }
    }
    __syncthreads();

    float O[8][4];
    #pragma unroll
    for (int i = 0; i < 8; i++)
        #pragma unroll
        for (int j = 0; j < 4; j++) O[i][j] = 0.f;
    float m0r = -1e30f, m1r = -1e30f, l0 = 0.f, l1 = 0.f;

    const uint32_t aKh = smem_u32(sKh), aKl = smem_u32(sKl);
    const uint32_t aVh = smem_u32(sVh), aVl = smem_u32(sVl);
    const int grp = lid >> 3, l8 = lid & 7;
    const int rAdd = ((grp >> 1) << 3) + l8;   // row-in-16 for b-frag x4
    const int cAdd = (grp & 1) << 3;           // col offset for b-frag x4

    // chunk prefetch registers
    float4 pk[2], pkl[2], pv[2], pvl[2];
    #pragma unroll
    for (int j = 0; j < 2; j++) {
        int cid = 2 * tid + j;
        int row = cid >> 3, off = (cid & 7) * 8;
        size_t ka = hoff + (size_t)row * HD_ + off;          // kt=0
        pk[j]  = *(const float4*)&g_khi[ka];
        pkl[j] = *(const float4*)&g_klo[ka];
        size_t va = voff + (size_t)row * N_ + off;           // kt=0
        pv[j]  = *(const float4*)&g_vhi[va];
        pvl[j] = *(const float4*)&g_vlo[va];
    }

    for (int ch = 0; ch < 32; ch++) {
        __syncthreads();
        #pragma unroll
        for (int j = 0; j < 2; j++) {
            int cid = 2 * tid + j;
            int row = cid >> 3, off = (cid & 7) * 8;
            *(float4*)&sKh[row * KSTR + off] = pk[j];
            *(float4*)&sKl[row * KSTR + off] = pkl[j];
            *(float4*)&sVh[row * KSTR + off] = pv[j];
            *(float4*)&sVl[row * KSTR + off] = pvl[j];
        }
        __syncthreads();
        if (ch < 31) {
            const int kt = (ch + 1) * 64;
            #pragma unroll
            for (int j = 0; j < 2; j++) {
                int cid = 2 * tid + j;
                int row = cid >> 3, off = (cid & 7) * 8;
                size_t ka = hoff + (size_t)(kt + row) * HD_ + off;
                pk[j]  = *(const float4*)&g_khi[ka];
                pkl[j] = *(const float4*)&g_klo[ka];
                size_t va = voff + (size_t)row * N_ + kt + off;
                pv[j]  = *(const float4*)&g_vhi[va];
                pvl[j] = *(const float4*)&g_vlo[va];
            }
        }

        // ---- S = Q K^T (triple bf16)
        float S[8][4];
        #pragma unroll
        for (int i = 0; i < 8; i++)
            #pragma unroll
            for (int j = 0; j < 4; j++) S[i][j] = 0.f;
        #pragma unroll
        for (int kk = 0; kk < 4; kk++) {
            #pragma unroll
            for (int ng = 0; ng < 4; ng++) {
                uint32_t kh[4], kl[4];
                uint32_t ad =
                    (uint32_t)((ng * 16 + rAdd) * KSTR + kk * 16 + cAdd) * 2;
                ldmx4(kh, aKh + ad);
                ldmx4(kl, aKl + ad);
                mma16816(S[2 * ng],     aqh[kk], kh);
                mma16816(S[2 * ng],     aql[kk], kh);
                mma16816(S[2 * ng],     aqh[kk], kl);
                mma16816(S[2 * ng + 1], aqh[kk], kh + 2);
                mma16816(S[2 * ng + 1], aql[kk], kh + 2);
                mma16816(S[2 * ng + 1], aqh[kk], kl + 2);
            }
        }

        // ---- online softmax (rows g, g+8; 4 lanes per row)
        float mx0 = S[0][0], mx1 = S[0][2];
        #pragma unroll
        for (int nt = 0; nt < 8; nt++) {
            mx0 = fmaxf(mx0, fmaxf(S[nt][0], S[nt][1]));
            mx1 = fmaxf(mx1, fmaxf(S[nt][2], S[nt][3]));
        }
        mx0 = fmaxf(mx0, __shfl_xor_sync(0xffffffffu, mx0, 1));
        mx0 = fmaxf(mx0, __shfl_xor_sync(0xffffffffu, mx0, 2));
        mx1 = fmaxf(mx1, __shfl_xor_sync(0xffffffffu, mx1, 1));
        mx1 = fmaxf(mx1, __shfl_xor_sync(0xffffffffu, mx1, 2));
        const float mn0 = fmaxf(m0r, mx0), mn1 = fmaxf(m1r, mx1);
        const float cr0 = __expf(m0r - mn0), cr1 = __expf(m1r - mn1);
        l0 *= cr0; l1 *= cr1;
        #pragma unroll
        for (int nt = 0; nt < 8; nt++) {
            O[nt][0] *= cr0; O[nt][1] *= cr0;
            O[nt][2] *= cr1; O[nt][3] *= cr1;
        }
        #pragma unroll
        for (int nt = 0; nt < 8; nt++) {
            S[nt][0] = __expf(S[nt][0] - mn0);
            S[nt][1] = __expf(S[nt][1] - mn0);
            S[nt][2] = __expf(S[nt][2] - mn1);
            S[nt][3] = __expf(S[nt][3] - mn1);
            l0 += S[nt][0] + S[nt][1];
            l1 += S[nt][2] + S[nt][3];
        }
        m0r = mn0; m1r = mn1;

        // ---- O += P V (triple bf16)
        #pragma unroll
        for (int kc = 0; kc < 4; kc++) {
            uint32_t ph[4], pl[4];
            split2(S[2 * kc][0],     S[2 * kc][1],     ph[0], pl[0]);
            split2(S[2 * kc][2],     S[2 * kc][3],     ph[1], pl[1]);
            split2(S[2 * kc + 1][0], S[2 * kc + 1][1], ph[2], pl[2]);
            split2(S[2 * kc + 1][2], S[2 * kc + 1][3], ph[3], pl[3]);
            #pragma unroll
            for (int ng = 0; ng < 4; ng++) {
                uint32_t vh[4], vl[4];
                uint32_t ad =
                    (uint32_t)((ng * 16 + rAdd) * KSTR + kc * 16 + cAdd) * 2;
                ldmx4(vh, aVh + ad);
                ldmx4(vl, aVl + ad);
                mma16816(O[2 * ng],     ph, vh);
                mma16816(O[2 * ng],     ph, vl);
                mma16816(O[2 * ng],     pl, vh);
                mma16816(O[2 * ng + 1], ph, vh + 2);
                mma16816(O[2 * ng + 1], ph, vl + 2);
                mma16816(O[2 * ng + 1], pl, vh + 2);
            }
        }
    }

    // ---- epilogue
    l0 += __shfl_xor_sync(0xffffffffu, l0, 1);
    l0 += __shfl_xor_sync(0xffffffffu, l0, 2);
    l1 += __shfl_xor_sync(0xffffffffu, l1, 1);
    l1 += __shfl_xor_sync(0xffffffffu, l1, 2);
    const float i0 = 1.f / l0, i1 = 1.f / l1;
    const int g = lid >> 2, t4 = lid & 3;
    const int r0 = q0 + wq * 16 + g;
    float* out0 = g_ao + ((size_t)b * N_ + r0) * C_ + h * HD_;
    float* out1 = out0 + 8 * C_;
    #pragma unroll
    for (int nt = 0; nt < 8; nt++) {
        const int col = nt * 8 + 2 * t4;
        float2 a, c2;
        a.x = O[nt][0] * i0; a.y = O[nt][1] * i0;
        c2.x = O[nt][2] * i1; c2.y = O[nt][3] * i1;
        *(float2*)&out0[col] = a;
        *(float2*)&out1[col] = c2;
    }
}

// ---------------------------------------------------------------------------
extern "C" void kernel_launch(void* const* d_in, const int* in_sizes, int n_in,
                              void* d_out, int out_size)
{
    const float* x      = (const float*)d_in[0];
    const float* qbias  = (const float*)d_in[1];
    const float* kbias  = (const float*)d_in[2];
    const float* vbias  = (const float*)d_in[3];
    const float* W_qkv  = (const float*)d_in[4];
    const float* b_qkv  = (const float*)d_in[5];
    const float* W_proj = (const float*)d_in[6];
    const float* b_proj = (const float*)d_in[7];
    float* out = (float*)d_out;

    tc_gemm<0><<<dim3(NC3 / 128, (B_ * N_) / 128), 256>>>(
        x, W_qkv, NC3, b_qkv, qbias, kbias, vbias, nullptr);
    attn_kernel<<<dim3(N_ / 128, H_, B_), 256>>>();
    tc_gemm<1><<<dim3(C_ / 128, (B_ * N_) / 128), 256>>>(
        nullptr, W_proj, C_, b_proj, nullptr, nullptr, nullptr, out);
}

// round 4
// speedup vs baseline: 3.1139x; 1.0029x over previous
#include <cuda_runtime.h>
#include <cuda_bf16.h>
#include <cstdint>

// Problem constants
#define B_  4
#define N_  2048
#define C_  768
#define H_  12
#define HD_ 64
#define NC3 2304
#define SCALE_ 0.125f

#define QKV_SZ ((size_t)B_ * H_ * N_ * HD_)   // 6291456

// Static scratch: bf16 hi/lo pairs for q,k,v; fp32 attention output
__device__ __nv_bfloat16 g_qhi[QKV_SZ], g_qlo[QKV_SZ];   // [B,H,N,HD], pre-scaled
__device__ __nv_bfloat16 g_khi[QKV_SZ], g_klo[QKV_SZ];   // [B,H,N,HD]
__device__ __nv_bfloat16 g_vhi[QKV_SZ], g_vlo[QKV_SZ];   // [B,H,HD,N] (transposed!)
__device__ float g_ao[(size_t)B_ * N_ * C_];              // [B,N,C]

// ---------------------------------------------------------------------------
// Helpers: portable tensor-core ISA (sm_80+, valid under plain sm_100)
// ---------------------------------------------------------------------------
__device__ __forceinline__ uint32_t smem_u32(const void* p) {
    uint32_t a;
    asm("{ .reg .u64 t; cvta.to.shared.u64 t, %1; cvt.u32.u64 %0, t; }"
        : "=r"(a) : "l"(p));
    return a;
}

__device__ __forceinline__ void ldmx4(uint32_t* r, uint32_t addr) {
    asm volatile("ldmatrix.sync.aligned.m8n8.x4.shared.b16 {%0,%1,%2,%3}, [%4];"
                 : "=r"(r[0]), "=r"(r[1]), "=r"(r[2]), "=r"(r[3]) : "r"(addr));
}
__device__ __forceinline__ void ldmx2t(uint32_t* r, uint32_t addr) {
    asm volatile("ldmatrix.sync.aligned.m8n8.x2.trans.shared.b16 {%0,%1}, [%2];"
                 : "=r"(r[0]), "=r"(r[1]) : "r"(addr));
}
__device__ __forceinline__ void mma16816(float* c, const uint32_t* a,
                                         const uint32_t* b) {
    asm volatile(
        "mma.sync.aligned.m16n8k16.row.col.f32.bf16.bf16.f32 "
        "{%0,%1,%2,%3}, {%4,%5,%6,%7}, {%8,%9}, {%0,%1,%2,%3};"
        : "+f"(c[0]), "+f"(c[1]), "+f"(c[2]), "+f"(c[3])
        : "r"(a[0]), "r"(a[1]), "r"(a[2]), "r"(a[3]), "r"(b[0]), "r"(b[1]));
}

// fp32 pair -> packed bf16 hi pair + lo (residual) pair
__device__ __forceinline__ void split2(float x, float y, uint32_t& hi, uint32_t& lo) {
    __nv_bfloat162 h = __floats2bfloat162_rn(x, y);
    float hx = __bfloat162float(h.x), hy = __bfloat162float(h.y);
    __nv_bfloat162 l = __floats2bfloat162_rn(x - hx, y - hy);
    hi = *(uint32_t*)&h;
    lo = *(uint32_t*)&l;
}

// ---------------------------------------------------------------------------
// Kernel 1/3: triple-bf16 HMMA GEMM. 128x128 CTA tile, 256 thr (8 warps 2x4,
// warp tile 64x32), K-stage 32, single smem buffer + register prefetch.
// MODE 0: qkv (A=x, epilogue -> hi/lo split q/k/v with biases, q*SCALE, v^T)
// MODE 1: proj (A=g_ao, epilogue -> d_out + b_proj)
// ---------------------------------------------------------------------------
#define ASTR 40     // A smem row stride (bf16 elems), 80B: conflict-free ldmatrix
#define BSTR 136    // B smem row stride, 272B

template <int MODE>
__global__ __launch_bounds__(256, 1) void tc_gemm(
    const float* __restrict__ Ain, const float* __restrict__ W, int ldb,
    const float* __restrict__ biasRow,
    const float* __restrict__ qb, const float* __restrict__ kb,
    const float* __restrict__ vb, float* __restrict__ outp)
{
    __shared__ __align__(16) __nv_bfloat16 sAh[128 * ASTR], sAl[128 * ASTR];
    __shared__ __align__(16) __nv_bfloat16 sBh[32 * BSTR],  sBl[32 * BSTR];

    const int tid = threadIdx.x, lid = tid & 31, wid = tid >> 5;
    const int wm = wid >> 2, wn = wid & 3;
    const int n0 = blockIdx.x * 128, m0 = blockIdx.y * 128;
    const float* A = (MODE == 1) ? g_ao : Ain;

    float c[4][4][4];
    #pragma unroll
    for (int i = 0; i < 4; i++)
        #pragma unroll
        for (int j = 0; j < 4; j++)
            #pragma unroll
            for (int k = 0; k < 4; k++) c[i][j][k] = 0.f;

    // prefetch mapping: A thread -> (row tid/2, k-half (tid&1)*16, 4xfloat4)
    //                   B thread -> (k-row tid/8, col 4*(tid&7) + 32j)
    const int ar = tid >> 1, akb = (tid & 1) * 16;
    const int br = tid >> 3, bcb = (tid & 7) * 4;
    const float* Ag = A + (size_t)(m0 + ar) * C_ + akb;
    const float* Bg = W + (size_t)br * ldb + n0 + bcb;

    float4 pa[4], pb[4];
    #pragma unroll
    for (int j = 0; j < 4; j++) {
        pa[j] = *(const float4*)(Ag + 4 * j);
        pb[j] = *(const float4*)(Bg + 32 * j);
    }

    const uint32_t aAh = smem_u32(sAh), aAl = smem_u32(sAl);
    const uint32_t aBh = smem_u32(sBh), aBl = smem_u32(sBl);

    for (int s = 0; s < C_ / 32; s++) {
        __syncthreads();
        #pragma unroll
        for (int j = 0; j < 4; j++) {
            uint32_t h0, l0v, h1, l1v;
            split2(pa[j].x, pa[j].y, h0, l0v);
            split2(pa[j].z, pa[j].w, h1, l1v);
            *(uint2*)&sAh[ar * ASTR + akb + 4 * j] = make_uint2(h0, h1);
            *(uint2*)&sAl[ar * ASTR + akb + 4 * j] = make_uint2(l0v, l1v);
            split2(pb[j].x, pb[j].y, h0, l0v);
            split2(pb[j].z, pb[j].w, h1, l1v);
            *(uint2*)&sBh[br * BSTR + bcb + 32 * j] = make_uint2(h0, h1);
            *(uint2*)&sBl[br * BSTR + bcb + 32 * j] = make_uint2(l0v, l1v);
        }
        __syncthreads();
        if (s + 1 < C_ / 32) {
            #pragma unroll
            for (int j = 0; j < 4; j++) {
                pa[j] = *(const float4*)(Ag + (s + 1) * 32 + 4 * j);
                pb[j] = *(const float4*)(Bg + (size_t)(s + 1) * 32 * ldb + 32 * j);
            }
        }
        #pragma unroll
        for (int kk = 0; kk < 2; kk++) {
            const int k0 = kk * 16;
            uint32_t ah[4][4], al[4][4];
            #pragma unroll
            for (int mt = 0; mt < 4; mt++) {
                int row = wm * 64 + mt * 16 + (lid & 15);
                int col = k0 + ((lid >> 4) << 3);
                ldmx4(ah[mt], aAh + (uint32_t)(row * ASTR + col) * 2);
                ldmx4(al[mt], aAl + (uint32_t)(row * ASTR + col) * 2);
            }
            uint32_t bh[4][2], bl[4][2];
            #pragma unroll
            for (int nt = 0; nt < 4; nt++) {
                int kr = k0 + (lid & 15);
                int col = wn * 32 + nt * 8;
                ldmx2t(bh[nt], aBh + (uint32_t)(kr * BSTR + col) * 2);
                ldmx2t(bl[nt], aBl + (uint32_t)(kr * BSTR + col) * 2);
            }
            #pragma unroll
            for (int mt = 0; mt < 4; mt++)
                #pragma unroll
                for (int nt = 0; nt < 4; nt++) {
                    mma16816(c[mt][nt], ah[mt], bh[nt]);
                    mma16816(c[mt][nt], al[mt], bh[nt]);
                    mma16816(c[mt][nt], ah[mt], bl[nt]);
                }
        }
    }

    // Epilogue (direct from fragments)
    const int g = lid >> 2, t4 = lid & 3;
    if (MODE == 0) {
        const int s3 = n0 / C_;
        const int loc0 = n0 - s3 * C_;
        #pragma unroll
        for (int mt = 0; mt < 4; mt++) {
            #pragma unroll
            for (int nt = 0; nt < 4; nt++) {
                const int colT = wn * 32 + nt * 8 + 2 * t4;
                const int loc = loc0 + colT;
                const int hh = loc >> 6, dd = loc & 63;
                const float b0v = biasRow[n0 + colT];
                const float b1v = biasRow[n0 + colT + 1];
                #pragma unroll
                for (int hf = 0; hf < 2; hf++) {
                    const int m = m0 + wm * 64 + mt * 16 + g + hf * 8;
                    const int bb = m >> 11, nn = m & 2047;
                    const size_t bidx =
                        (((size_t)bb * H_ + hh) * N_ + nn) * HD_ + dd;
                    float v0 = c[mt][nt][2 * hf] + b0v;
                    float v1 = c[mt][nt][2 * hf + 1] + b1v;
                    if (s3 == 0) {
                        v0 = (v0 + qb[bidx]) * SCALE_;
                        v1 = (v1 + qb[bidx + 1]) * SCALE_;
                        uint32_t hi, lo;
                        split2(v0, v1, hi, lo);
                        *(uint32_t*)&g_qhi[bidx] = hi;
                        *(uint32_t*)&g_qlo[bidx] = lo;
                    } else if (s3 == 1) {
                        v0 += kb[bidx];
                        v1 += kb[bidx + 1];
                        uint32_t hi, lo;
                        split2(v0, v1, hi, lo);
                        *(uint32_t*)&g_khi[bidx] = hi;
                        *(uint32_t*)&g_klo[bidx] = lo;
                    } else {
                        v0 += vb[bidx];
                        v1 += vb[bidx + 1];
                        const size_t vix =
                            (((size_t)bb * H_ + hh) * HD_ + dd) * N_ + nn;
                        __nv_bfloat16 h0 = __float2bfloat16_rn(v0);
                        __nv_bfloat16 h1 = __float2bfloat16_rn(v1);
                        g_vhi[vix] = h0;
                        g_vlo[vix] = __float2bfloat16_rn(v0 - __bfloat162float(h0));
                        g_vhi[vix + N_] = h1;
                        g_vlo[vix + N_] = __float2bfloat16_rn(v1 - __bfloat162float(h1));
                    }
                }
            }
        }
    } else {
        #pragma unroll
        for (int mt = 0; mt < 4; mt++)
            #pragma unroll
            for (int nt = 0; nt < 4; nt++) {
                const int colT = wn * 32 + nt * 8 + 2 * t4;
                const float b0v = biasRow[n0 + colT];
                const float b1v = biasRow[n0 + colT + 1];
                #pragma unroll
                for (int hf = 0; hf < 2; hf++) {
                    const int m = m0 + wm * 64 + mt * 16 + g + hf * 8;
                    float2 r;
                    r.x = c[mt][nt][2 * hf] + b0v;
                    r.y = c[mt][nt][2 * hf + 1] + b1v;
                    *(float2*)&outp[(size_t)m * C_ + n0 + colT] = r;
                }
            }
    }
}

// ---------------------------------------------------------------------------
// Kernel 2: HMMA flash attention. CTA = 128 q-rows, 8 warps x 16 rows.
// 64-key chunks; triple-bf16 QK^T and PV; online softmax on fragments.
// ---------------------------------------------------------------------------
#define KSTR 72   // smem row stride (bf16): 144B -> conflict-free ldmatrix

__global__ __launch_bounds__(256, 1) void attn_kernel()
{
    __shared__ __align__(16) __nv_bfloat16 sm[4 * 64 * KSTR];  // 36864B
    __nv_bfloat16* sKh = sm;
    __nv_bfloat16* sKl = sm + 64 * KSTR;
    __nv_bfloat16* sVh = sm + 2 * 64 * KSTR;
    __nv_bfloat16* sVl = sm + 3 * 64 * KSTR;
    __nv_bfloat16* sQh = sm;                 // Q staging aliases (pre-loop only)
    __nv_bfloat16* sQl = sm + 128 * KSTR;

    const int tid = threadIdx.x, lid = tid & 31, wq = tid >> 5;
    const int qt = blockIdx.x, h = blockIdx.y, b = blockIdx.z;
    const size_t hoff = (size_t)(b * H_ + h) * N_ * HD_;   // q,k base
    const size_t voff = (size_t)(b * H_ + h) * HD_ * N_;   // v^T base
    const int q0 = qt * 128;

    // ---- stage Q (hi/lo) and capture fragments in registers
    #pragma unroll
    for (int j = 0; j < 4; j++) {
        int cid = tid + 256 * j;
        int row = cid >> 3, off = (cid & 7) * 8;
        size_t ga = hoff + (size_t)(q0 + row) * HD_ + off;
        *(float4*)&sQh[row * KSTR + off] = *(const float4*)&g_qhi[ga];
        *(float4*)&sQl[row * KSTR + off] = *(const float4*)&g_qlo[ga];
    }
    __syncthreads();
    uint32_t aqh[4][4], aql[4][4];
    {
        const uint32_t bH = smem_u32(sQh), bL = smem_u32(sQl);
        int row = wq * 16 + (lid & 15);
        int colb = (lid >> 4) << 3;
        #pragma unroll
        for (int kk = 0; kk < 4; kk++) {
            ldmx4(aqh[kk], bH + (uint32_t)(row * KSTR + kk * 16 + colb) * 2);
            ldmx4(aql[kk], bL + (uint32_t)(row * KSTR + kk * 16 + colb) * 2);
        }
    }
    __syncthreads();

    float O[8][4];
    #pragma unroll
    for (int i = 0; i < 8; i++)
        #pragma unroll
        for (int j = 0; j < 4; j++) O[i][j] = 0.f;
    float m0r = -1e30f, m1r = -1e30f, l0 = 0.f, l1 = 0.f;

    const uint32_t aKh = smem_u32(sKh), aKl = smem_u32(sKl);
    const uint32_t aVh = smem_u32(sVh), aVl = smem_u32(sVl);
    const int grp = lid >> 3, l8 = lid & 7;
    const int rAdd = ((grp >> 1) << 3) + l8;   // row-in-16 for b-frag x4
    const int cAdd = (grp & 1) << 3;           // col offset for b-frag x4

    // chunk prefetch registers
    float4 pk[2], pkl[2], pv[2], pvl[2];
    #pragma unroll
    for (int j = 0; j < 2; j++) {
        int cid = 2 * tid + j;
        int row = cid >> 3, off = (cid & 7) * 8;
        size_t ka = hoff + (size_t)row * HD_ + off;          // kt=0
        pk[j]  = *(const float4*)&g_khi[ka];
        pkl[j] = *(const float4*)&g_klo[ka];
        size_t va = voff + (size_t)row * N_ + off;           // kt=0
        pv[j]  = *(const float4*)&g_vhi[va];
        pvl[j] = *(const float4*)&g_vlo[va];
    }

    for (int ch = 0; ch < 32; ch++) {
        __syncthreads();
        #pragma unroll
        for (int j = 0; j < 2; j++) {
            int cid = 2 * tid + j;
            int row = cid >> 3, off = (cid & 7) * 8;
            *(float4*)&sKh[row * KSTR + off] = pk[j];
            *(float4*)&sKl[row * KSTR + off] = pkl[j];
            *(float4*)&sVh[row * KSTR + off] = pv[j];
            *(float4*)&sVl[row * KSTR + off] = pvl[j];
        }
        __syncthreads();
        if (ch < 31) {
            const int kt = (ch + 1) * 64;
            #pragma unroll
            for (int j = 0; j < 2; j++) {
                int cid = 2 * tid + j;
                int row = cid >> 3, off = (cid & 7) * 8;
                size_t ka = hoff + (size_t)(kt + row) * HD_ + off;
                pk[j]  = *(const float4*)&g_khi[ka];
                pkl[j] = *(const float4*)&g_klo[ka];
                size_t va = voff + (size_t)row * N_ + kt + off;
                pv[j]  = *(const float4*)&g_vhi[va];
                pvl[j] = *(const float4*)&g_vlo[va];
            }
        }

        // ---- S = Q K^T (triple bf16)
        float S[8][4];
        #pragma unroll
        for (int i = 0; i < 8; i++)
            #pragma unroll
            for (int j = 0; j < 4; j++) S[i][j] = 0.f;
        #pragma unroll
        for (int kk = 0; kk < 4; kk++) {
            #pragma unroll
            for (int ng = 0; ng < 4; ng++) {
                uint32_t kh[4], kl[4];
                uint32_t ad =
                    (uint32_t)((ng * 16 + rAdd) * KSTR + kk * 16 + cAdd) * 2;
                ldmx4(kh, aKh + ad);
                ldmx4(kl, aKl + ad);
                mma16816(S[2 * ng],     aqh[kk], kh);
                mma16816(S[2 * ng],     aql[kk], kh);
                mma16816(S[2 * ng],     aqh[kk], kl);
                mma16816(S[2 * ng + 1], aqh[kk], kh + 2);
                mma16816(S[2 * ng + 1], aql[kk], kh + 2);
                mma16816(S[2 * ng + 1], aqh[kk], kl + 2);
            }
        }

        // ---- online softmax (rows g, g+8; 4 lanes per row)
        float mx0 = S[0][0], mx1 = S[0][2];
        #pragma unroll
        for (int nt = 0; nt < 8; nt++) {
            mx0 = fmaxf(mx0, fmaxf(S[nt][0], S[nt][1]));
            mx1 = fmaxf(mx1, fmaxf(S[nt][2], S[nt][3]));
        }
        mx0 = fmaxf(mx0, __shfl_xor_sync(0xffffffffu, mx0, 1));
        mx0 = fmaxf(mx0, __shfl_xor_sync(0xffffffffu, mx0, 2));
        mx1 = fmaxf(mx1, __shfl_xor_sync(0xffffffffu, mx1, 1));
        mx1 = fmaxf(mx1, __shfl_xor_sync(0xffffffffu, mx1, 2));
        const float mn0 = fmaxf(m0r, mx0), mn1 = fmaxf(m1r, mx1);
        const float cr0 = __expf(m0r - mn0), cr1 = __expf(m1r - mn1);
        l0 *= cr0; l1 *= cr1;
        #pragma unroll
        for (int nt = 0; nt < 8; nt++) {
            O[nt][0] *= cr0; O[nt][1] *= cr0;
            O[nt][2] *= cr1; O[nt][3] *= cr1;
        }
        #pragma unroll
        for (int nt = 0; nt < 8; nt++) {
            S[nt][0] = __expf(S[nt][0] - mn0);
            S[nt][1] = __expf(S[nt][1] - mn0);
            S[nt][2] = __expf(S[nt][2] - mn1);
            S[nt][3] = __expf(S[nt][3] - mn1);
            l0 += S[nt][0] + S[nt][1];
            l1 += S[nt][2] + S[nt][3];
        }
        m0r = mn0; m1r = mn1;

        // ---- O += P V (triple bf16)
        #pragma unroll
        for (int kc = 0; kc < 4; kc++) {
            uint32_t ph[4], pl[4];
            split2(S[2 * kc][0],     S[2 * kc][1],     ph[0], pl[0]);
            split2(S[2 * kc][2],     S[2 * kc][3],     ph[1], pl[1]);
            split2(S[2 * kc + 1][0], S[2 * kc + 1][1], ph[2], pl[2]);
            split2(S[2 * kc + 1][2], S[2 * kc + 1][3], ph[3], pl[3]);
            #pragma unroll
            for (int ng = 0; ng < 4; ng++) {
                uint32_t vh[4], vl[4];
                uint32_t ad =
                    (uint32_t)((ng * 16 + rAdd) * KSTR + kc * 16 + cAdd) * 2;
                ldmx4(vh, aVh + ad);
                ldmx4(vl, aVl + ad);
                mma16816(O[2 * ng],     ph, vh);
                mma16816(O[2 * ng],     ph, vl);
                mma16816(O[2 * ng],     pl, vh);
                mma16816(O[2 * ng + 1], ph, vh + 2);
                mma16816(O[2 * ng + 1], ph, vl + 2);
                mma16816(O[2 * ng + 1], pl, vh + 2);
            }
        }
    }

    // ---- epilogue
    l0 += __shfl_xor_sync(0xffffffffu, l0, 1);
    l0 += __shfl_xor_sync(0xffffffffu, l0, 2);
    l1 += __shfl_xor_sync(0xffffffffu, l1, 1);
    l1 += __shfl_xor_sync(0xffffffffu, l1, 2);
    const float i0 = 1.f / l0, i1 = 1.f / l1;
    const int g = lid >> 2, t4 = lid & 3;
    const int r0 = q0 + wq * 16 + g;
    float* out0 = g_ao + ((size_t)b * N_ + r0) * C_ + h * HD_;
    float* out1 = out0 + 8 * C_;
    #pragma unroll
    for (int nt = 0; nt < 8; nt++) {
        const int col = nt * 8 + 2 * t4;
        float2 a, c2;
        a.x = O[nt][0] * i0; a.y = O[nt][1] * i0;
        c2.x = O[nt][2] * i1; c2.y = O[nt][3] * i1;
        *(float2*)&out0[col] = a;
        *(float2*)&out1[col] = c2;
    }
}

// ---------------------------------------------------------------------------
extern "C" void kernel_launch(void* const* d_in, const int* in_sizes, int n_in,
                              void* d_out, int out_size)
{
    const float* x      = (const float*)d_in[0];
    const float* qbias  = (const float*)d_in[1];
    const float* kbias  = (const float*)d_in[2];
    const float* vbias  = (const float*)d_in[3];
    const float* W_qkv  = (const float*)d_in[4];
    const float* b_qkv  = (const float*)d_in[5];
    const float* W_proj = (const float*)d_in[6];
    const float* b_proj = (const float*)d_in[7];
    float* out = (float*)d_out;

    tc_gemm<0><<<dim3(NC3 / 128, (B_ * N_) / 128), 256>>>(
        x, W_qkv, NC3, b_qkv, qbias, kbias, vbias, nullptr);
    attn_kernel<<<dim3(N_ / 128, H_, B_), 256>>>();
    tc_gemm<1><<<dim3(C_ / 128, (B_ * N_) / 128), 256>>>(
        nullptr, W_proj, C_, b_proj, nullptr, nullptr, nullptr, out);
}